// round 13
// baseline (speedup 1.0000x reference)
#include <cuda_runtime.h>
#include <cstddef>

#define Bn     4
#define Cn     64
#define Hn     512
#define Wn     512
#define NSPIX  256
#define HW     (Hn*Wn)

typedef unsigned long long ull;

// scratch: triple-buffered accumulators (iter it: reads (it+2)%3, writes it%3,
// zeros (it+1)%3 — all three distinct, kernel boundaries order cross-iter use)
__device__ float g_numer3[3][Bn*NSPIX*Cn];
__device__ float g_denom3[3][Bn*NSPIX];

// ---- packed fp32x2 helpers ----
__device__ __forceinline__ ull f2_pack(float a, float b) {
    ull r; asm("mov.b64 %0, {%1,%2};" : "=l"(r) : "f"(a), "f"(b)); return r;
}
__device__ __forceinline__ void f2_unpack(ull v, float& a, float& b) {
    asm("mov.b64 {%0,%1}, %2;" : "=f"(a), "=f"(b) : "l"(v));
}
__device__ __forceinline__ void ffma2(ull& d, ull a, ull b) {
    asm("fma.rn.f32x2 %0, %1, %2, %0;" : "+l"(d) : "l"(a), "l"(b));
}
__device__ __forceinline__ void fadd2(ull& d, ull a) {
    asm("add.rn.f32x2 %0, %0, %1;" : "+l"(d) : "l"(a));
}

// shared layout (float offsets), 128-px tile; W (8 rows) overlays dead G
#define OFF_G    0                      // [9][64] centroids (dead after phase-1 dots)
#define OFF_W    0                      // [8][128] weights k<8 (written after G dies)
#define OFF_GSQ  1024                   // [12]
#define OFF_DRED 1036                   // [9][4]
#define OFF_F    1072                   // [64][130] pixel-scalar floats
#define FS       130                    // FS/2=65 odd -> pair reads conflict-free
#define SMEM_FLOATS (1072 + 64*FS)      // 9392 floats = 37568 B  (6 CTAs/SM)
#define SMEM_BYTES  (SMEM_FLOATS*4)
#define PSTRIDE 584                     // partial stride per warp-group (overlay on f)

__device__ __forceinline__ int nbr_of(int R, int Cc, int k) {
    return (R + k/3 - 1)*16 + (Cc + k%3 - 1);
}

// ---------------------------------------------------------------------------
// init: seed buf2 with block SUMS (denom=1024 -> mean on first divide);
// zero buf0 (iter0 writes) and buf1
// ---------------------------------------------------------------------------
__global__ void init_kernel(const float* __restrict__ f)
{
    __shared__ float sm[256];
    const int s = blockIdx.x, b = blockIdx.y;
    const int tid = threadIdx.x;
    const int c = tid & 63, part = tid >> 6;
    const int R = s >> 4, Cc = s & 15;
    const int y0 = R*32 + part*8, x0 = Cc*32;
    const float* fp = f + ((size_t)(b*Cn + c))*HW + (size_t)y0*Wn + x0;

    float sum = 0.f;
    for (int yy = 0; yy < 8; yy++) {
        const float4* r = (const float4*)(fp + (size_t)yy*Wn);
        #pragma unroll
        for (int x4 = 0; x4 < 8; x4++) {
            float4 v = r[x4];
            sum += (v.x + v.y) + (v.z + v.w);
        }
    }
    sm[tid] = sum;

    int gid = ((blockIdx.y*gridDim.x) + blockIdx.x)*256 + tid;   // 0..262143
    if (gid < Bn*NSPIX*Cn) g_numer3[0][gid] = 0.f;
    if (gid >= Bn*NSPIX*Cn && gid < 2*Bn*NSPIX*Cn)
        g_numer3[1][gid - Bn*NSPIX*Cn] = 0.f;
    if (gid < 2*Bn*NSPIX) ((float*)g_denom3)[gid] = 0.f;         // denom3[0],[1]

    __syncthreads();
    if (tid < 64) {
        float t = sm[tid] + sm[64+tid] + sm[128+tid] + sm[192+tid];
        g_numer3[2][(b*NSPIX + s)*Cn + tid] = t;                 // raw sum
    }
    if (tid == 64) g_denom3[2][b*NSPIX + s] = 1024.f;
}

// ---------------------------------------------------------------------------
// fused iteration kernel.  grid=(8,256,4)  block=128 (4x32 pixel tile)
// ---------------------------------------------------------------------------
__global__ __launch_bounds__(128, 6)
void ssn_iter_kernel(const float* __restrict__ f,
                     float* __restrict__ out_labels,
                     int it, int last)
{
    extern __shared__ float sm[];
    const int tid = threadIdx.x;
    const int bb = blockIdx.z, cell = blockIdx.y, q = blockIdx.x;
    const int R = cell >> 4, Cc = cell & 15;
    const int y0 = R*32 + q*4, x0 = Cc*32;
    const int bufR = (it + 2) % 3, bufW = it % 3, bufZ = (it + 1) % 3;

    // zero our slice of next iteration's write buffer (untouched this iter)
    {
        int cid = (((bb*NSPIX + cell) << 3) + q);        // 0..8191
        if (tid < 8) g_numer3[bufZ][cid*8 + tid] = 0.f;
        if (tid == 8 && cid < Bn*NSPIX) g_denom3[bufZ][cid] = 0.f;
    }

    unsigned vmask = 0;
    #pragma unroll
    for (int k = 0; k < 9; k++) {
        int rr = R + k/3 - 1, cc = Cc + (k%3) - 1;
        if ((rr >= 0) & (rr < 16) & (cc >= 0) & (cc < 16)) vmask |= 1u << k;
    }

    // stage g = numer/denom via float4; gsq via half-warp shuffle reduce
    // (each 16-lane half owns exactly one k-row of 16 float4s)
    const float* nsrc = g_numer3[bufR];
    const float* dsrc = g_denom3[bufR];
    {
        int idx = tid;                               // 0..127 -> k=0..7
        int k = idx >> 4;
        int nb = nbr_of(R, Cc, k);
        float4 v = make_float4(0.f, 0.f, 0.f, 0.f);
        if (vmask >> k & 1) {
            float r = 1.0f / (dsrc[bb*NSPIX + nb] + 1e-16f);
            float4 u = ((const float4*)(nsrc + (size_t)(bb*NSPIX + nb)*Cn))[idx & 15];
            v.x = u.x*r; v.y = u.y*r; v.z = u.z*r; v.w = u.w*r;
        }
        ((float4*)&sm[OFF_G])[idx] = v;
        float s2 = (v.x*v.x + v.y*v.y) + (v.z*v.z + v.w*v.w);
        s2 += __shfl_down_sync(0xffffffffu, s2, 8, 16);
        s2 += __shfl_down_sync(0xffffffffu, s2, 4, 16);
        s2 += __shfl_down_sync(0xffffffffu, s2, 2, 16);
        s2 += __shfl_down_sync(0xffffffffu, s2, 1, 16);
        if ((tid & 15) == 0) sm[OFF_GSQ + k] = s2;
    }
    if (tid < 16) {                                  // idx 128..143 -> k=8
        int nb = nbr_of(R, Cc, 8);
        float4 v = make_float4(0.f, 0.f, 0.f, 0.f);
        if (vmask >> 8 & 1) {
            float r = 1.0f / (dsrc[bb*NSPIX + nb] + 1e-16f);
            float4 u = ((const float4*)(nsrc + (size_t)(bb*NSPIX + nb)*Cn))[tid];
            v.x = u.x*r; v.y = u.y*r; v.z = u.z*r; v.w = u.w*r;
        }
        ((float4*)&sm[OFF_G])[128 + tid] = v;
        float s2 = (v.x*v.x + v.y*v.y) + (v.z*v.z + v.w*v.w);
        s2 += __shfl_down_sync(0x0000ffffu, s2, 8, 16);
        s2 += __shfl_down_sync(0x0000ffffu, s2, 4, 16);
        s2 += __shfl_down_sync(0x0000ffffu, s2, 2, 16);
        s2 += __shfl_down_sync(0x0000ffffu, s2, 1, 16);
        if (tid == 0) sm[OFF_GSQ + 8] = s2;
    }
    __syncthreads();

    // ---- phase 1: per-pixel stream; scalar staging; channel-packed dots
    const int p = tid;
    ull acc[9], sv = 0ull;
    #pragma unroll
    for (int k = 0; k < 9; k++) acc[k] = 0ull;
    {
        const float* fp = f + ((size_t)bb*Cn)*HW
                            + (size_t)(y0 + (p >> 5))*Wn + (x0 + (p & 31));
        #pragma unroll 4
        for (int cs = 0; cs < 16; cs++) {
            const int c = cs*4;
            float v0 = fp[(size_t)(c+0)*HW];
            float v1 = fp[(size_t)(c+1)*HW];
            float v2 = fp[(size_t)(c+2)*HW];
            float v3 = fp[(size_t)(c+3)*HW];
            sm[OFF_F + (c+0)*FS + p] = v0;      // conflict-free STS.32
            sm[OFF_F + (c+1)*FS + p] = v1;
            sm[OFF_F + (c+2)*FS + p] = v2;
            sm[OFF_F + (c+3)*FS + p] = v3;
            ull p01 = f2_pack(v0, v1);
            ull p23 = f2_pack(v2, v3);
            ffma2(sv, p01, p01);
            ffma2(sv, p23, p23);
            #pragma unroll
            for (int k = 0; k < 9; k++) {
                ulonglong2 g2 = *(const ulonglong2*)&sm[OFF_G + k*64 + c];  // broadcast
                ffma2(acc[k], p01, g2.x);
                ffma2(acc[k], p23, g2.y);
            }
        }
    }
    __syncthreads();   // f tile complete; G dead from here (W overlays)

    // ---- softmax per pixel (registers)
    float w[9];
    {
        float sa, sb; f2_unpack(sv, sa, sb);
        const float sv_s = sa + sb;
        float dmin = 3.0e38f;
        #pragma unroll
        for (int k = 0; k < 9; k++) {
            float a, b; f2_unpack(acc[k], a, b);
            float d = (vmask >> k & 1) ? (sv_s - 2.f*(a+b) + sm[OFF_GSQ + k]) : 3.0e38f;
            w[k] = d;
            dmin = fminf(dmin, d);
        }
        if (last) {
            int kb = 0; float bd = w[0];
            #pragma unroll
            for (int k = 1; k < 9; k++) if (w[k] < bd) { bd = w[k]; kb = k; }
            out_labels[(size_t)bb*HW + (size_t)(y0 + (p>>5))*Wn + (x0 + (p&31))]
                = (float)nbr_of(R, Cc, kb);
        }
        float s = 0.f;
        #pragma unroll
        for (int k = 0; k < 9; k++) { float e = __expf(dmin - w[k]); w[k] = e; s += e; }
        float inv = 1.f / s;
        #pragma unroll
        for (int k = 0; k < 9; k++) w[k] *= inv;
    }

    // store only w[0..7] (w[8] reconstructed from sum rule in phase 2)
    #pragma unroll
    for (int k = 0; k < 8; k++) sm[OFF_W + k*128 + p] = w[k];

    // denominators: 9 block-wide sums (exact register weights)
    #pragma unroll
    for (int k = 0; k < 9; k++) {
        float s = w[k];
        s += __shfl_down_sync(0xffffffffu, s, 16);
        s += __shfl_down_sync(0xffffffffu, s, 8);
        s += __shfl_down_sync(0xffffffffu, s, 4);
        s += __shfl_down_sync(0xffffffffu, s, 2);
        s += __shfl_down_sync(0xffffffffu, s, 1);
        if ((tid & 31) == 0) sm[OFF_DRED + k*4 + (tid >> 5)] = s;
    }
    __syncthreads();   // w + dred visible
    if (tid < 9 && (vmask >> tid & 1)) {
        const float* dr = &sm[OFF_DRED + tid*4];
        float s = (dr[0] + dr[1]) + (dr[2] + dr[3]);
        atomicAdd(&g_denom3[bufW][bb*NSPIX + nbr_of(R, Cc, tid)], s);
    }

    // ---- phase 2: 8 weighted rows + unweighted pixel-sum row
    // lane = channels (l, l+32); warp grp owns 32 pixels (16 pairs)
    const int l   = tid & 31;
    const int grp = tid >> 5;
    ull m[16], msA = 0ull, msB = 0ull;
    #pragma unroll
    for (int k = 0; k < 16; k++) m[k] = 0ull;
    {
        const int pb = grp*32;
        #pragma unroll 2
        for (int jp = 0; jp < 8; jp++) {
            const int px = pb + jp*4;        // 4 pixels = 2 pairs per step
            ull A0 = *(const ull*)&sm[OFF_F +  l      *FS + px    ];
            ull A1 = *(const ull*)&sm[OFF_F +  l      *FS + px + 2];
            ull B0 = *(const ull*)&sm[OFF_F + (l + 32)*FS + px    ];
            ull B1 = *(const ull*)&sm[OFF_F + (l + 32)*FS + px + 2];
            fadd2(msA, A0); fadd2(msA, A1);
            fadd2(msB, B0); fadd2(msB, B1);
            #pragma unroll
            for (int k = 0; k < 8; k++) {
                ulonglong2 wv = *(const ulonglong2*)&sm[OFF_W + k*128 + px]; // broadcast
                ffma2(m[k],     wv.x, A0);
                ffma2(m[k],     wv.y, A1);
                ffma2(m[k + 8], wv.x, B0);
                ffma2(m[k + 8], wv.y, B1);
            }
        }
    }
    __syncthreads();   // all f reads done -> overlay partials on f region

    {   // scalar partials; slot 8 via sum rule: M8 = sum_p f - sum_{k<8} Mk
        float* part = &sm[OFF_F];
        float a, b, sA = 0.f, sB = 0.f;
        #pragma unroll
        for (int k = 0; k < 8; k++) {
            f2_unpack(m[k], a, b);
            float pk = a + b;
            part[(size_t)grp*PSTRIDE + k*64 + l] = pk;
            sA += pk;
            f2_unpack(m[k+8], a, b);
            pk = a + b;
            part[(size_t)grp*PSTRIDE + k*64 + l + 32] = pk;
            sB += pk;
        }
        f2_unpack(msA, a, b);
        part[(size_t)grp*PSTRIDE + 8*64 + l]      = (a + b) - sA;
        f2_unpack(msB, a, b);
        part[(size_t)grp*PSTRIDE + 8*64 + l + 32] = (a + b) - sB;
    }
    __syncthreads();

    {   // reduce 576 slots over 4 groups, then global RED.ADD
        const float* part = &sm[OFF_F];
        for (int s = tid; s < 576; s += 128) {
            float sum = part[s];
            #pragma unroll
            for (int g = 1; g < 4; g++) sum += part[(size_t)g*PSTRIDE + s];
            int k = s >> 6, c = s & 63;
            int nb = (vmask >> k & 1) ? nbr_of(R, Cc, k) : 0;
            atomicAdd(&g_numer3[bufW][(bb*NSPIX + nb)*Cn + c], sum);  // invalid k adds 0.0
        }
    }
}

// ---------------------------------------------------------------------------
__global__ void final_kernel(float* __restrict__ out_spix)
{
    int idx = blockIdx.x*256 + threadIdx.x;     // 65536
    // iter 4 wrote buffer 4%3 = 1
    out_spix[idx] = g_numer3[1][idx] / (g_denom3[1][idx >> 6] + 1e-16f);
}

// ---------------------------------------------------------------------------
extern "C" void kernel_launch(void* const* d_in, const int* in_sizes, int n_in,
                              void* d_out, int out_size)
{
    const float* f = (const float*)d_in[0];
    float* out        = (float*)d_out;
    float* out_spix   = out;                       // (4,256,64)
    float* out_labels = out + Bn*NSPIX*Cn;         // (4,262144)

    cudaFuncSetAttribute(ssn_iter_kernel,
                         cudaFuncAttributeMaxDynamicSharedMemorySize, SMEM_BYTES);

    init_kernel<<<dim3(NSPIX, Bn), 256>>>(f);
    for (int it = 0; it < 5; it++)
        ssn_iter_kernel<<<dim3(8, NSPIX, Bn), 128, SMEM_BYTES>>>(
            f, out_labels, it, it == 4);
    final_kernel<<<256, 256>>>(out_spix);
}

// round 14
// speedup vs baseline: 1.1289x; 1.1289x over previous
#include <cuda_runtime.h>
#include <cstddef>

#define Bn     4
#define Cn     64
#define Hn     512
#define Wn     512
#define NSPIX  256
#define HW     (Hn*Wn)

typedef unsigned long long ull;

// scratch
__device__ float g_spix [Bn*NSPIX*Cn];
__device__ float g_numer[Bn*NSPIX*Cn];
__device__ float g_denom2[2][Bn*NSPIX];
__device__ float g_gsq  [Bn*NSPIX];

// ---- packed fp32x2 helpers ----
__device__ __forceinline__ ull f2_pack(float a, float b) {
    ull r; asm("mov.b64 %0, {%1,%2};" : "=l"(r) : "f"(a), "f"(b)); return r;
}
__device__ __forceinline__ void f2_unpack(ull v, float& a, float& b) {
    asm("mov.b64 {%0,%1}, %2;" : "=f"(a), "=f"(b) : "l"(v));
}
__device__ __forceinline__ void ffma2(ull& d, ull a, ull b) {
    asm("fma.rn.f32x2 %0, %1, %2, %0;" : "+l"(d) : "l"(a), "l"(b));
}
__device__ __forceinline__ void fadd2(ull& d, ull a) {
    asm("add.rn.f32x2 %0, %0, %1;" : "+l"(d) : "l"(a));
}
__device__ __forceinline__ void grid_dep_wait() {
    asm volatile("griddepcontrol.wait;" ::: "memory");
}

// shared layout (float offsets), 128-px tile; W (8 rows) overlays dead G
#define OFF_G    0                      // [9][64] centroids (dead after phase-1 dots)
#define OFF_W    0                      // [8][128] weights k<8 (written after G dies)
#define OFF_GSQ  1024                   // [12]
#define OFF_DRED 1036                   // [9][4]
#define OFF_F    1072                   // [64][130] pixel-scalar floats
#define FS       130                    // FS/2=65 odd -> pair reads conflict-free
#define SMEM_FLOATS (1072 + 64*FS)      // 9392 floats = 37568 B  (6 CTAs/SM)
#define SMEM_BYTES  (SMEM_FLOATS*4)
#define PSTRIDE 584                     // partial stride per warp-group (overlay on f)

__device__ __forceinline__ int nbr_of(int R, int Cc, int k) {
    return (R + k/3 - 1)*16 + (Cc + k%3 - 1);
}

// ---------------------------------------------------------------------------
__global__ void init_kernel(const float* __restrict__ f)
{
    __shared__ float sm[256];
    __shared__ float red[8];
    const int s = blockIdx.x, b = blockIdx.y;
    const int tid = threadIdx.x;
    const int c = tid & 63, part = tid >> 6;
    const int R = s >> 4, Cc = s & 15;
    const int y0 = R*32 + part*8, x0 = Cc*32;
    const float* fp = f + ((size_t)(b*Cn + c))*HW + (size_t)y0*Wn + x0;

    float sum = 0.f;
    for (int yy = 0; yy < 8; yy++) {
        const float4* r = (const float4*)(fp + (size_t)yy*Wn);
        #pragma unroll
        for (int x4 = 0; x4 < 8; x4++) {
            float4 v = r[x4];
            sum += (v.x + v.y) + (v.z + v.w);
        }
    }
    sm[tid] = sum;

    int gid = ((blockIdx.y*gridDim.x) + blockIdx.x)*256 + tid;
    if (gid < Bn*NSPIX*Cn) g_numer[gid] = 0.f;
    if (gid < 2*Bn*NSPIX)  ((float*)g_denom2)[gid] = 0.f;

    __syncthreads();
    float val = 0.f;
    if (tid < 64) {
        float t = sm[tid] + sm[64+tid] + sm[128+tid] + sm[192+tid];
        val = t * (1.0f/1024.0f);
        g_spix[(b*NSPIX + s)*Cn + tid] = val;
    }
    // ||g||^2 via full-block reduce (val=0 for tid>=64)
    float s2 = val*val;
    #pragma unroll
    for (int o = 16; o; o >>= 1) s2 += __shfl_down_sync(0xffffffffu, s2, o);
    if ((tid & 31) == 0) red[tid >> 5] = s2;
    __syncthreads();
    if (tid == 0) {
        float t = ((red[0]+red[1]) + (red[2]+red[3]))
                + ((red[4]+red[5]) + (red[6]+red[7]));
        g_gsq[b*NSPIX + s] = t;
    }
}

// ---------------------------------------------------------------------------
// fused iteration kernel.  grid=(8,256,4)  block=128 (4x32 pixel tile)
// ---------------------------------------------------------------------------
__global__ __launch_bounds__(128, 6)
void ssn_iter_kernel(const float* __restrict__ f,
                     float* __restrict__ out_labels,
                     int it, int last)
{
    extern __shared__ float sm[];
    const int tid = threadIdx.x;
    const int bb = blockIdx.z, cell = blockIdx.y, q = blockIdx.x;
    const int R = cell >> 4, Cc = cell & 15;
    const int y0 = R*32 + q*4, x0 = Cc*32;
    const int par = it & 1;

    unsigned vmask = 0;
    #pragma unroll
    for (int k = 0; k < 9; k++) {
        int rr = R + k/3 - 1, cc = Cc + (k%3) - 1;
        if ((rr >= 0) & (rr < 16) & (cc >= 0) & (cc < 16)) vmask |= 1u << k;
    }

    grid_dep_wait();   // predecessor (init/update) wrote g_spix/g_gsq

    // stage g via float4 (zero-filled invalid) + gsq via 9 LDG
    for (int idx = tid; idx < 144; idx += 128) {
        int k = idx >> 4;
        int nb = nbr_of(R, Cc, k);
        float4 v = make_float4(0.f, 0.f, 0.f, 0.f);
        if (vmask >> k & 1)
            v = ((const float4*)(g_spix + (size_t)(bb*NSPIX + nb)*Cn))[idx & 15];
        ((float4*)&sm[OFF_G])[idx] = v;
    }
    if (tid < 9) {
        int nb = nbr_of(R, Cc, tid);
        sm[OFF_GSQ + tid] = (vmask >> tid & 1) ? g_gsq[bb*NSPIX + nb] : 0.f;
    }
    __syncthreads();

    // ---- phase 1: per-pixel stream; scalar staging; channel-packed dots
    const int p = tid;
    ull acc[9], sv = 0ull;
    #pragma unroll
    for (int k = 0; k < 9; k++) acc[k] = 0ull;
    {
        const float* fp = f + ((size_t)bb*Cn)*HW
                            + (size_t)(y0 + (p >> 5))*Wn + (x0 + (p & 31));
        #pragma unroll 4
        for (int cs = 0; cs < 16; cs++) {
            const int c = cs*4;
            float v0 = fp[(size_t)(c+0)*HW];
            float v1 = fp[(size_t)(c+1)*HW];
            float v2 = fp[(size_t)(c+2)*HW];
            float v3 = fp[(size_t)(c+3)*HW];
            sm[OFF_F + (c+0)*FS + p] = v0;      // conflict-free STS.32
            sm[OFF_F + (c+1)*FS + p] = v1;
            sm[OFF_F + (c+2)*FS + p] = v2;
            sm[OFF_F + (c+3)*FS + p] = v3;
            ull p01 = f2_pack(v0, v1);
            ull p23 = f2_pack(v2, v3);
            ffma2(sv, p01, p01);
            ffma2(sv, p23, p23);
            #pragma unroll
            for (int k = 0; k < 9; k++) {
                ulonglong2 g2 = *(const ulonglong2*)&sm[OFF_G + k*64 + c];  // broadcast
                ffma2(acc[k], p01, g2.x);
                ffma2(acc[k], p23, g2.y);
            }
        }
    }
    __syncthreads();   // f tile complete; G dead from here (W overlays)

    // ---- softmax per pixel (registers)
    float w[9];
    {
        float sa, sb; f2_unpack(sv, sa, sb);
        const float sv_s = sa + sb;
        float dmin = 3.0e38f;
        #pragma unroll
        for (int k = 0; k < 9; k++) {
            float a, b; f2_unpack(acc[k], a, b);
            float d = (vmask >> k & 1) ? (sv_s - 2.f*(a+b) + sm[OFF_GSQ + k]) : 3.0e38f;
            w[k] = d;
            dmin = fminf(dmin, d);
        }
        if (last) {
            int kb = 0; float bd = w[0];
            #pragma unroll
            for (int k = 1; k < 9; k++) if (w[k] < bd) { bd = w[k]; kb = k; }
            out_labels[(size_t)bb*HW + (size_t)(y0 + (p>>5))*Wn + (x0 + (p&31))]
                = (float)nbr_of(R, Cc, kb);
        }
        float s = 0.f;
        #pragma unroll
        for (int k = 0; k < 9; k++) { float e = __expf(dmin - w[k]); w[k] = e; s += e; }
        float inv = 1.f / s;
        #pragma unroll
        for (int k = 0; k < 9; k++) w[k] *= inv;
    }

    // store only w[0..7] (w[8] reconstructed from sum rule in phase 2)
    #pragma unroll
    for (int k = 0; k < 8; k++) sm[OFF_W + k*128 + p] = w[k];

    // denominators: 9 block-wide sums (exact register weights)
    #pragma unroll
    for (int k = 0; k < 9; k++) {
        float s = w[k];
        s += __shfl_down_sync(0xffffffffu, s, 16);
        s += __shfl_down_sync(0xffffffffu, s, 8);
        s += __shfl_down_sync(0xffffffffu, s, 4);
        s += __shfl_down_sync(0xffffffffu, s, 2);
        s += __shfl_down_sync(0xffffffffu, s, 1);
        if ((tid & 31) == 0) sm[OFF_DRED + k*4 + (tid >> 5)] = s;
    }
    __syncthreads();   // w + dred visible
    if (tid < 9 && (vmask >> tid & 1)) {
        const float* dr = &sm[OFF_DRED + tid*4];
        float s = (dr[0] + dr[1]) + (dr[2] + dr[3]);
        atomicAdd(&g_denom2[par][bb*NSPIX + nbr_of(R, Cc, tid)], s);
    }

    // ---- phase 2: 8 weighted rows + unweighted pixel-sum row
    // lane = channels (l, l+32); warp grp owns 32 pixels (16 pairs)
    const int l   = tid & 31;
    const int grp = tid >> 5;
    ull m[16], msA = 0ull, msB = 0ull;
    #pragma unroll
    for (int k = 0; k < 16; k++) m[k] = 0ull;
    {
        const int pb = grp*32;
        #pragma unroll 2
        for (int jp = 0; jp < 8; jp++) {
            const int px = pb + jp*4;        // 4 pixels = 2 pairs per step
            ull A0 = *(const ull*)&sm[OFF_F +  l      *FS + px    ];
            ull A1 = *(const ull*)&sm[OFF_F +  l      *FS + px + 2];
            ull B0 = *(const ull*)&sm[OFF_F + (l + 32)*FS + px    ];
            ull B1 = *(const ull*)&sm[OFF_F + (l + 32)*FS + px + 2];
            fadd2(msA, A0); fadd2(msA, A1);
            fadd2(msB, B0); fadd2(msB, B1);
            #pragma unroll
            for (int k = 0; k < 8; k++) {
                ulonglong2 wv = *(const ulonglong2*)&sm[OFF_W + k*128 + px]; // broadcast
                ffma2(m[k],     wv.x, A0);
                ffma2(m[k],     wv.y, A1);
                ffma2(m[k + 8], wv.x, B0);
                ffma2(m[k + 8], wv.y, B1);
            }
        }
    }
    __syncthreads();   // all f reads done -> overlay partials on f region

    {   // scalar partials; slot 8 via sum rule: M8 = sum_p f - sum_{k<8} Mk
        float* part = &sm[OFF_F];
        float a, b, sA = 0.f, sB = 0.f;
        #pragma unroll
        for (int k = 0; k < 8; k++) {
            f2_unpack(m[k], a, b);
            float pk = a + b;
            part[(size_t)grp*PSTRIDE + k*64 + l] = pk;
            sA += pk;
            f2_unpack(m[k+8], a, b);
            pk = a + b;
            part[(size_t)grp*PSTRIDE + k*64 + l + 32] = pk;
            sB += pk;
        }
        f2_unpack(msA, a, b);
        part[(size_t)grp*PSTRIDE + 8*64 + l]      = (a + b) - sA;
        f2_unpack(msB, a, b);
        part[(size_t)grp*PSTRIDE + 8*64 + l + 32] = (a + b) - sB;
    }
    __syncthreads();

    {   // reduce 576 slots over 4 groups, then global RED.ADD
        const float* part = &sm[OFF_F];
        for (int s = tid; s < 576; s += 128) {
            float sum = part[s];
            #pragma unroll
            for (int g = 1; g < 4; g++) sum += part[(size_t)g*PSTRIDE + s];
            int k = s >> 6, c = s & 63;
            int nb = (vmask >> k & 1) ? nbr_of(R, Cc, k) : 0;
            atomicAdd(&g_numer[(bb*NSPIX + nb)*Cn + c], sum);  // invalid k adds 0.0
        }
    }
}

// ---------------------------------------------------------------------------
__global__ void update_kernel(float* __restrict__ out_spix, int it, int last)
{
    __shared__ float red[8];
    const int tid = threadIdx.x;
    int idx = blockIdx.x*256 + tid;             // 65536 total; 4 spix per block
    int par = it & 1;
    grid_dep_wait();                            // iter's atomics must be complete
    float val = g_numer[idx] / (g_denom2[par][idx >> 6] + 1e-16f);
    g_spix[idx] = val;
    if (last) out_spix[idx] = val;
    g_numer[idx] = 0.f;
    if (idx < Bn*NSPIX) g_denom2[1 - par][idx] = 0.f;

    // ||g||^2 per spix
    float s2 = val*val;
    #pragma unroll
    for (int o = 16; o; o >>= 1) s2 += __shfl_down_sync(0xffffffffu, s2, o);
    if ((tid & 31) == 0) red[tid >> 5] = s2;
    __syncthreads();
    if (tid < 4)
        g_gsq[blockIdx.x*4 + tid] = red[2*tid] + red[2*tid + 1];
}

// ---------------------------------------------------------------------------
static void launch_pdl(void* fn, dim3 grid, dim3 block, size_t smem,
                       void** args)
{
    cudaLaunchConfig_t cfg = {};
    cfg.gridDim = grid;
    cfg.blockDim = block;
    cfg.dynamicSmemBytes = smem;
    cfg.stream = 0;
    cudaLaunchAttribute attr[1];
    attr[0].id = cudaLaunchAttributeProgrammaticStreamSerialization;
    attr[0].val.programmaticStreamSerializationAllowed = 1;
    cfg.attrs = attr;
    cfg.numAttrs = 1;
    cudaLaunchKernelExC(&cfg, fn, args);
}

extern "C" void kernel_launch(void* const* d_in, const int* in_sizes, int n_in,
                              void* d_out, int out_size)
{
    const float* f = (const float*)d_in[0];
    float* out        = (float*)d_out;
    float* out_spix   = out;                       // (4,256,64)
    float* out_labels = out + Bn*NSPIX*Cn;         // (4,262144)

    cudaFuncSetAttribute(ssn_iter_kernel,
                         cudaFuncAttributeMaxDynamicSharedMemorySize, SMEM_BYTES);

    init_kernel<<<dim3(NSPIX, Bn), 256>>>(f);
    for (int it = 0; it < 5; it++) {
        int last = (it == 4);
        {
            void* args[4] = { (void*)&f, (void*)&out_labels, &it, &last };
            launch_pdl((void*)ssn_iter_kernel, dim3(8, NSPIX, Bn), dim3(128),
                       SMEM_BYTES, args);
        }
        {
            void* args[3] = { (void*)&out_spix, &it, &last };
            launch_pdl((void*)update_kernel, dim3(256), dim3(256), 0, args);
        }
    }
}